// round 1
// baseline (speedup 1.0000x reference)
#include <cuda_runtime.h>
#include <cstddef>

#define N_AQI 35
#define N_MEO 18
#define NTOT  53
#define F_OUT 64
#define CTXD  60
#define BATCH 4096
#define NEGV  (-1e12f)
#define LALPHA 0.2f

// ---------------- batch-independent precomputed state ----------------
__device__ float g_bias[NTOT * NTOT];          // ctx_s + ctx_t + adj_norm * a[248]
__device__ unsigned int g_mask[NTOT][2];       // adjacency bitmask per row
__device__ float g_wsrc[2][2][26];             // [rowtype][colblock][k]  = W_u @ a[0:64]
__device__ float g_wdst[2][2][26];             // [coltype][rowblock][k]  = W_u @ a[124:188]

__global__ void precompute_kernel(
    const float* __restrict__ ctx,
    const float* __restrict__ adj_norm,
    const float* __restrict__ a_aa, const float* __restrict__ a_am,
    const float* __restrict__ a_ma, const float* __restrict__ a_mm,
    const float* __restrict__ W_ua, const float* __restrict__ W_um,
    const int*   __restrict__ adj)
{
    __shared__ float s_cs[NTOT][2];   // ctx part of s, per colblock
    __shared__ float s_ct[NTOT][2];   // ctx part of t, per rowblock
    const int tid = threadIdx.x;
    const float* A[2][2] = {{a_aa, a_am}, {a_ma, a_mm}};  // [rowblock][colblock]

    // ctx_s[i][cb] = ctx[i] . a_{rb(i),cb}[64:124];  ctx_t[j][rb] = ctx[j] . a_{rb,cb(j)}[188:248]
    for (int id = tid; id < NTOT * 4; id += blockDim.x) {
        int i = id % NTOT;
        int sel = id / NTOT;          // 0,1 -> s (cb); 2,3 -> t (rb)
        if (sel < 2) {
            int rb = (i < N_AQI) ? 0 : 1;
            const float* a = A[rb][sel];
            float acc = 0.f;
            for (int c = 0; c < CTXD; c++) acc += ctx[i * CTXD + c] * a[64 + c];
            s_cs[i][sel] = acc;
        } else {
            int rb = sel - 2;
            int cb = (i < N_AQI) ? 0 : 1;
            const float* a = A[rb][cb];
            float acc = 0.f;
            for (int c = 0; c < CTXD; c++) acc += ctx[i * CTXD + c] * a[188 + c];
            s_ct[i][rb] = acc;
        }
    }

    // Folded weight-a vectors: 2(which)*2*2*26 = 208 entries
    for (int id = tid; id < 2 * 2 * 2 * 26; id += blockDim.x) {
        int k = id % 26;
        int r = id / 26;          // 0..7
        int which = r >> 2;       // 0: src, 1: dst
        int t0 = (r >> 1) & 1;    // src: rowtype / dst: coltype  (selects W)
        int t1 = r & 1;           // src: colblock / dst: rowblock
        const float* W = (t0 == 0) ? W_ua : W_um;
        int K = (t0 == 0) ? 24 : 26;
        float acc = 0.f;
        if (k < K) {
            const float* a = (which == 0) ? A[t0][t1] : A[t1][t0];
            int off = (which == 0) ? 0 : 124;
            for (int f = 0; f < 64; f++) acc += W[k * 64 + f] * a[off + f];
        }
        if (which == 0) g_wsrc[t0][t1][k] = acc;
        else            g_wdst[t0][t1][k] = acc;
    }

    // adjacency bitmask
    for (int i = tid; i < NTOT; i += blockDim.x) {
        unsigned int m0 = 0, m1 = 0;
        for (int j = 0; j < 32; j++)   if (adj[i * NTOT + j] > 0) m0 |= (1u << j);
        for (int j = 32; j < NTOT; j++) if (adj[i * NTOT + j] > 0) m1 |= (1u << (j - 32));
        g_mask[i][0] = m0; g_mask[i][1] = m1;
    }
    __syncthreads();

    // bias matrix
    for (int id = tid; id < NTOT * NTOT; id += blockDim.x) {
        int i = id / NTOT, j = id % NTOT;
        int rb = (i < N_AQI) ? 0 : 1;
        int cb = (j < N_AQI) ? 0 : 1;
        g_bias[id] = s_cs[i][cb] + s_ct[j][rb] + adj_norm[id] * A[rb][cb][248];
    }
}

// ---------------- main kernel: one CTA per batch element ----------------
__global__ __launch_bounds__(256) void hgat_kernel(
    const float* __restrict__ aqi_inp, const float* __restrict__ meo_inp,
    const float* __restrict__ W_xa,    const float* __restrict__ W_xm,
    const float* __restrict__ aqi_idE, const float* __restrict__ aqi_monthE,
    const float* __restrict__ aqi_weekdayE, const float* __restrict__ aqi_hourE,
    const float* __restrict__ meo_windE, const float* __restrict__ meo_idE,
    const float* __restrict__ meo_monthE, const float* __restrict__ meo_weekdayE,
    const float* __restrict__ meo_hourE,
    const int* __restrict__ aqi_ex, const int* __restrict__ meo_ex,
    float* __restrict__ out)
{
    __shared__ float s_Wxa[16 * 64];
    __shared__ float s_Wxm[16 * 64];
    __shared__ float s_fullA[36 * 24];     // padded row for register tiling
    __shared__ float s_fullM[20 * 26];
    __shared__ float s_projx[NTOT * 64];   // heter_attri
    __shared__ float s_attn[56 * 56];      // padded rows for reg-tiled phase 4
    __shared__ float s_S[NTOT * 2];
    __shared__ float s_T[NTOT * 2];

    const int tid = threadIdx.x;
    const int b = blockIdx.x;

    // ---- Phase 0: stage weights + build full feature rows (with embedding gathers) ----
    for (int i = tid; i < 16 * 64; i += 256) { s_Wxa[i] = W_xa[i]; s_Wxm[i] = W_xm[i]; }

    for (int id = tid; id < N_AQI * 24; id += 256) {
        int i = id / 24, c = id % 24;
        float v;
        if (c < 16) v = aqi_inp[((size_t)b * N_AQI + i) * 16 + c];
        else {
            int e = (c - 16) >> 1, comp = (c - 16) & 1;
            int ix = aqi_ex[((size_t)b * N_AQI + i) * 4 + e];
            const float* tab = (e == 0) ? aqi_idE : (e == 1) ? aqi_monthE
                             : (e == 2) ? aqi_weekdayE : aqi_hourE;
            v = tab[ix * 2 + comp];
        }
        s_fullA[i * 24 + c] = v;
    }
    for (int id = tid; id < N_MEO * 26; id += 256) {
        int i = id / 26, c = id % 26;
        float v;
        if (c < 16) v = meo_inp[((size_t)b * N_MEO + i) * 16 + c];
        else {
            int e = (c - 16) >> 1, comp = (c - 16) & 1;
            int ix = meo_ex[((size_t)b * N_MEO + i) * 5 + e];
            const float* tab = (e == 0) ? meo_windE : (e == 1) ? meo_idE
                             : (e == 2) ? meo_monthE : (e == 3) ? meo_weekdayE : meo_hourE;
            v = tab[ix * 2 + comp];
        }
        s_fullM[i * 26 + c] = v;
    }
    __syncthreads();

    // ---- Phase 1: proj_x (heter_attri), register-tiled: 4 row-groups x 64 feats ----
    {
        const int f = tid & 63, rg = tid >> 6;
        float acc[9];
        const int nA = (N_AQI - rg + 3) >> 2;   // 9 or 8
        #pragma unroll
        for (int r = 0; r < 9; r++) acc[r] = 0.f;
        #pragma unroll
        for (int k = 0; k < 16; k++) {
            float w = s_Wxa[k * 64 + f];
            #pragma unroll
            for (int r = 0; r < 9; r++)
                acc[r] += s_fullA[(rg + 4 * r) * 24 + k] * w;
        }
        for (int r = 0; r < nA; r++) s_projx[(rg + 4 * r) * 64 + f] = acc[r];

        float accm[5];
        const int nM = (N_MEO - rg + 3) >> 2;   // 5 or 4
        #pragma unroll
        for (int r = 0; r < 5; r++) accm[r] = 0.f;
        #pragma unroll
        for (int k = 0; k < 16; k++) {
            float w = s_Wxm[k * 64 + f];
            #pragma unroll
            for (int r = 0; r < 5; r++)
                accm[r] += s_fullM[(rg + 4 * r) * 26 + k] * w;
        }
        for (int r = 0; r < nM; r++) s_projx[(N_AQI + rg + 4 * r) * 64 + f] = accm[r];
    }

    // ---- Phase 2: S[i][cb], T[j][rb] via folded weight vectors (212 short dots) ----
    if (tid < NTOT * 4) {
        int i = tid % NTOT;
        int sel = tid / NTOT;     // 0,1: S(cb); 2,3: T(rb)
        int rt = (i < N_AQI) ? 0 : 1;
        const float* xr = (rt == 0) ? &s_fullA[i * 24] : &s_fullM[(i - N_AQI) * 26];
        int K = (rt == 0) ? 24 : 26;
        float acc = 0.f;
        if (sel < 2) {
            const float* wv = g_wsrc[rt][sel];
            for (int k = 0; k < K; k++) acc += xr[k] * wv[k];
            s_S[i * 2 + sel] = acc;
        } else {
            const float* wv = g_wdst[rt][sel - 2];
            for (int k = 0; k < K; k++) acc += xr[k] * wv[k];
            s_T[i * 2 + (sel - 2)] = acc;
        }
    }
    __syncthreads();

    // ---- Phase 3: masked leaky-relu scores + softmax, one warp per row ----
    {
        const int w = tid >> 5, lane = tid & 31;
        for (int i = w; i < NTOT; i += 8) {
            const int rb = (i < N_AQI) ? 0 : 1;
            const unsigned int m0 = g_mask[i][0], m1 = g_mask[i][1];
            const int j1 = lane, j2 = lane + 32;
            float e1, e2;
            {
                int cb = (j1 < N_AQI) ? 0 : 1;
                float v = s_S[i * 2 + cb] + s_T[j1 * 2 + rb] + g_bias[i * NTOT + j1];
                v = (v >= 0.f) ? v : LALPHA * v;
                e1 = ((m0 >> j1) & 1u) ? v : NEGV;
            }
            if (j2 < NTOT) {
                int cb = 1;   // j2 >= 32 could still be < 35
                cb = (j2 < N_AQI) ? 0 : 1;
                float v = s_S[i * 2 + cb] + s_T[j2 * 2 + rb] + g_bias[i * NTOT + j2];
                v = (v >= 0.f) ? v : LALPHA * v;
                e2 = ((m1 >> (j2 - 32)) & 1u) ? v : NEGV;
            } else {
                e2 = -3.4e38f;
            }
            float mx = fmaxf(e1, e2);
            #pragma unroll
            for (int o = 16; o > 0; o >>= 1) mx = fmaxf(mx, __shfl_xor_sync(0xffffffffu, mx, o));
            float p1 = __expf(e1 - mx);
            float p2 = (j2 < NTOT) ? __expf(e2 - mx) : 0.f;
            float sum = p1 + p2;
            #pragma unroll
            for (int o = 16; o > 0; o >>= 1) sum += __shfl_xor_sync(0xffffffffu, sum, o);
            float inv = 1.f / sum;
            s_attn[i * 56 + j1] = p1 * inv;
            if (j2 < NTOT) s_attn[i * 56 + j2] = p2 * inv;
        }
    }
    __syncthreads();

    // ---- Phase 4: out = attn @ proj_x, reg-tiled 7 rows x 2 feats per lane ----
    {
        const int w = tid >> 5, lane = tid & 31;
        float acc0[7], acc1[7];
        #pragma unroll
        for (int r = 0; r < 7; r++) { acc0[r] = 0.f; acc1[r] = 0.f; }
        for (int j = 0; j < NTOT; j++) {
            float p0 = s_projx[j * 64 + lane];
            float p1 = s_projx[j * 64 + lane + 32];
            #pragma unroll
            for (int r = 0; r < 7; r++) {
                float a = s_attn[(w + 8 * r) * 56 + j];   // padded rows: garbage rows unused
                acc0[r] += a * p0;
                acc1[r] += a * p1;
            }
        }
        #pragma unroll
        for (int r = 0; r < 7; r++) {
            int i = w + 8 * r;
            if (i < NTOT) {
                float* dst;
                if (i < N_AQI) dst = out + ((size_t)b * N_AQI + i) * 64;
                else dst = out + (size_t)BATCH * N_AQI * 64 + ((size_t)b * N_MEO + (i - N_AQI)) * 64;
                dst[lane]      = acc0[r];
                dst[lane + 32] = acc1[r];
            }
        }
    }
}

extern "C" void kernel_launch(void* const* d_in, const int* in_sizes, int n_in,
                              void* d_out, int out_size)
{
    const float* aqi_inp      = (const float*)d_in[0];
    const float* meo_inp      = (const float*)d_in[1];
    const float* context_feat = (const float*)d_in[2];
    const float* adj_norm     = (const float*)d_in[3];
    const float* aqi_idE      = (const float*)d_in[4];
    const float* aqi_monthE   = (const float*)d_in[5];
    const float* aqi_weekdayE = (const float*)d_in[6];
    const float* aqi_hourE    = (const float*)d_in[7];
    const float* meo_windE    = (const float*)d_in[8];
    const float* meo_idE      = (const float*)d_in[9];
    const float* meo_monthE   = (const float*)d_in[10];
    const float* meo_weekdayE = (const float*)d_in[11];
    const float* meo_hourE    = (const float*)d_in[12];
    const float* W_xa         = (const float*)d_in[13];
    const float* W_xm         = (const float*)d_in[14];
    const float* W_ua         = (const float*)d_in[15];
    const float* W_um         = (const float*)d_in[16];
    const float* a_aa         = (const float*)d_in[17];
    const float* a_am         = (const float*)d_in[18];
    const float* a_ma         = (const float*)d_in[19];
    const float* a_mm         = (const float*)d_in[20];
    const int*   aqi_ex       = (const int*)d_in[21];
    const int*   meo_ex       = (const int*)d_in[22];
    const int*   adj          = (const int*)d_in[23];
    float* out = (float*)d_out;

    precompute_kernel<<<1, 256>>>(context_feat, adj_norm,
                                  a_aa, a_am, a_ma, a_mm,
                                  W_ua, W_um, adj);
    hgat_kernel<<<BATCH, 256>>>(aqi_inp, meo_inp, W_xa, W_xm,
                                aqi_idE, aqi_monthE, aqi_weekdayE, aqi_hourE,
                                meo_windE, meo_idE, meo_monthE, meo_weekdayE, meo_hourE,
                                aqi_ex, meo_ex, out);
}